// round 16
// baseline (speedup 1.0000x reference)
#include <cuda_runtime.h>
#include <cuda_fp16.h>
#include <math.h>
#include <stdint.h>

#define NB 16
#define NS 1024
#define ND 128
#define NH 4
#define LNEPS 1e-5f
#define SCALE 0.08838834764831845f

// Scratch (device globals: allocation-free per harness rules)
__device__ __half g_xh[NB*NS*ND];          // fp16 copy of x (written by ln_partial)
__device__ __half g_qh[NB*NH*NS*ND];       // [bh][s][d], scale folded, fp16
__device__ __half g_kh[NB*NH*NS*ND];       // [bh][s][d_slot16], fp16
__device__ __half g_vth[NB*NH*NS*ND];      // [bh][d][s_slot16], fp16
__device__ __half g_ctx[NB*NH*NS*ND];      // fp16 ctx
__device__ __half g_win_h[NH*3*ND*ND];     // W_in rows, fp16, slot16 k
__device__ __half g_wout_h[NH*ND*ND];      // W_out rows, fp16, slot16 k
__device__ float  g_off[NB*NH*3*ND];       // per-batch fused bias: b_in - mean*rstd*wsum
__device__ float  g_psum[NB*8];
__device__ float  g_psum2[NB*8];
__device__ float  g_mean[NB];
__device__ float  g_rstd[NB];
__device__ unsigned long long g_mbits[NH*NS*16];
__device__ int    g_edge64;

// slot16: within each 16-group, order 0,1,8,9,2,3,10,11,4,5,12,13,6,7,14,15
__device__ __forceinline__ int slot16(int k) {
    return (k < 8) ? ((k >> 1) * 4 + (k & 1)) : (((k - 8) >> 1) * 4 + 2 + (k & 1));
}

__device__ __forceinline__ void mma16(float& d0, float& d1, float& d2, float& d3,
                                      uint32_t a0, uint32_t a1, uint32_t a2, uint32_t a3,
                                      uint32_t b0, uint32_t b1) {
    asm volatile("mma.sync.aligned.m16n8k16.row.col.f32.f16.f16.f32 "
                 "{%0,%1,%2,%3}, {%4,%5,%6,%7}, {%8,%9}, {%0,%1,%2,%3};"
                 : "+f"(d0), "+f"(d1), "+f"(d2), "+f"(d3)
                 : "r"(a0), "r"(a1), "r"(a2), "r"(a3), "r"(b0), "r"(b1));
}

__device__ __forceinline__ void cp16(void* dst_smem, const void* src_gmem) {
    uint32_t d = (uint32_t)__cvta_generic_to_shared(dst_smem);
    asm volatile("cp.async.cg.shared.global [%0], [%1], 16;" :: "r"(d), "l"(src_gmem));
}

__device__ __forceinline__ uint32_t h2u(__half2 h) {
    return *reinterpret_cast<uint32_t*>(&h);
}

// ---------------------------------------------------------------------------
// K1a: LN partial sums + fp16 conversion of x (128 blocks: 8 per batch)
// ---------------------------------------------------------------------------
__global__ void ln_partial_kernel(const float* __restrict__ x) {
    const int b = blockIdx.x >> 3;
    const int part = blockIdx.x & 7;
    const size_t base4 = (size_t)b * NS * ND / 4 + part * 4096;
    const float4* xb = (const float4*)x + base4;
    __half2* xh = (__half2*)g_xh + base4 * 2;
    float s = 0.f, ss = 0.f;
    #pragma unroll
    for (int i = 0; i < 16; i++) {
        float4 v = xb[i * 256 + threadIdx.x];
        s  += v.x + v.y + v.z + v.w;
        ss += v.x*v.x + v.y*v.y + v.z*v.z + v.w*v.w;
        xh[2*(i*256 + threadIdx.x)]     = __floats2half2_rn(v.x, v.y);
        xh[2*(i*256 + threadIdx.x) + 1] = __floats2half2_rn(v.z, v.w);
    }
    __shared__ float sh[256], sh2[256];
    sh[threadIdx.x] = s; sh2[threadIdx.x] = ss;
    __syncthreads();
    for (int o = 128; o > 0; o >>= 1) {
        if (threadIdx.x < o) {
            sh[threadIdx.x]  += sh[threadIdx.x + o];
            sh2[threadIdx.x] += sh2[threadIdx.x + o];
        }
        __syncthreads();
    }
    if (threadIdx.x == 0) {
        g_psum[blockIdx.x]  = sh[0];
        g_psum2[blockIdx.x] = sh2[0];
    }
}

// K1b: finalize mean/rstd + edge dtype sniff (1 block)
__global__ void ln_final_kernel(const int* __restrict__ edge) {
    int t = threadIdx.x;
    if (t < NB) {
        float s = 0.f, ss = 0.f;
        #pragma unroll
        for (int i = 0; i < 8; i++) { s += g_psum[t*8 + i]; ss += g_psum2[t*8 + i]; }
        float inv_n = 1.f / (float)(NS * ND);
        float mu  = s * inv_n;
        float var = ss * inv_n - mu * mu;
        g_mean[t] = mu;
        g_rstd[t] = rsqrtf(var + LNEPS);
    } else if (t == 32) {
        int any = 0;
        #pragma unroll
        for (int i = 0; i < 64; i++) any |= edge[2*i + 1];
        g_edge64 = (any == 0) ? 1 : 0;
    }
}

// ---------------------------------------------------------------------------
// K1c: prep — edge bitmasks, fused per-batch bias, fp16 slot16 weight copies
// ---------------------------------------------------------------------------
__global__ void prep_kernel(const int* __restrict__ edge,
                            const float* __restrict__ W_in,
                            const float* __restrict__ b_in,
                            const float* __restrict__ W_out) {
    int blk = blockIdx.x;
    if (blk < 64) {
        int idx = blk * 256 + threadIdx.x;
        int s = idx >> 4, t64 = idx & 15;
        unsigned long long m0 = 0, m1 = 0, m2 = 0, m3 = 0;
        if (g_edge64) {
            const int4* p = (const int4*)(edge + 2*((size_t)s*NS + t64*64));
            #pragma unroll
            for (int i = 0; i < 32; i++) {
                int4 v = p[i];
                unsigned long long b0 = 1ull << (2*i), b1 = 1ull << (2*i+1);
                if (v.x == 1) m0 |= b0;  if (v.z == 1) m0 |= b1;
                if (v.x == 2) m1 |= b0;  if (v.z == 2) m1 |= b1;
                if (v.x == 3) m2 |= b0;  if (v.z == 3) m2 |= b1;
                if (v.x == 4) m3 |= b0;  if (v.z == 4) m3 |= b1;
            }
        } else {
            const int4* p = (const int4*)(edge + ((size_t)s*NS + t64*64));
            #pragma unroll
            for (int i = 0; i < 16; i++) {
                int4 v = p[i];
                int e[4] = {v.x, v.y, v.z, v.w};
                #pragma unroll
                for (int q = 0; q < 4; q++) {
                    unsigned long long b = 1ull << (4*i + q);
                    if (e[q] == 1) m0 |= b;
                    if (e[q] == 2) m1 |= b;
                    if (e[q] == 3) m2 |= b;
                    if (e[q] == 4) m3 |= b;
                }
            }
        }
        g_mbits[(0*NS + s)*16 + t64] = m0;
        g_mbits[(1*NS + s)*16 + t64] = m1;
        g_mbits[(2*NS + s)*16 + t64] = m2;
        g_mbits[(3*NS + s)*16 + t64] = m3;
    } else if (blk < 70) {
        int col = (blk - 64) * 256 + threadIdx.x;
        float s = 0.f;
        const float4* p = (const float4*)(W_in + (size_t)col * ND);
        #pragma unroll
        for (int i = 0; i < 32; i++) {
            float4 v = p[i];
            s += v.x + v.y + v.z + v.w;
        }
        float bias = b_in[col];
        #pragma unroll
        for (int bb = 0; bb < NB; bb++) {
            float mr = g_mean[bb] * g_rstd[bb];
            g_off[bb * (NH*3*ND) + col] = bias - mr * s;
        }
    } else {
        int row = (blk - 70) * 256 + threadIdx.x;
        const float* src;
        __half* dst;
        if (row < 1536) { src = W_in  + (size_t)row * ND;          dst = g_win_h  + (size_t)row * ND; }
        else            { src = W_out + (size_t)(row - 1536) * ND; dst = g_wout_h + (size_t)(row - 1536) * ND; }
        #pragma unroll
        for (int g = 0; g < 8; g++) {
            float4 A0 = *(const float4*)&src[16*g];
            float4 A1 = *(const float4*)&src[16*g + 4];
            float4 A2 = *(const float4*)&src[16*g + 8];
            float4 A3 = *(const float4*)&src[16*g + 12];
            __half2 h[8];
            h[0] = __floats2half2_rn(A0.x, A0.y);
            h[1] = __floats2half2_rn(A2.x, A2.y);
            h[2] = __floats2half2_rn(A0.z, A0.w);
            h[3] = __floats2half2_rn(A2.z, A2.w);
            h[4] = __floats2half2_rn(A1.x, A1.y);
            h[5] = __floats2half2_rn(A3.x, A3.y);
            h[6] = __floats2half2_rn(A1.z, A1.w);
            h[7] = __floats2half2_rn(A3.z, A3.w);
            *(uint4*)&dst[16*g]     = *(const uint4*)&h[0];
            *(uint4*)&dst[16*g + 8] = *(const uint4*)&h[4];
        }
    }
}

// ---------------------------------------------------------------------------
// Projection kernels: fp16 mma.m16n8k16; A fp16-staged, B fp16 slot16.
// qkv: 4-slot depth-3 cp.async pipeline (mirrors attn's proven schedule).
// ---------------------------------------------------------------------------
#define APH 136
#define BPH 144
#define BSLOT (64*BPH)
#define PROJ_SMEM_BYTES (128*APH*2 + 4*64*BPH*2)   // 34816 + 73728 = 108544

__device__ __forceinline__ void load_b_async(const __half* __restrict__ Wsrc,
                                             int rowbase, __half* Bslot, int tid) {
    #pragma unroll
    for (int i = 0; i < 4; i++) {
        int q = i * 256 + tid;
        int row = q >> 4, c = (q & 15) * 8;
        cp16(&Bslot[row*BPH + c], &Wsrc[(size_t)(rowbase + row) * ND + c]);
    }
}

__global__ __launch_bounds__(256, 2) void qkv_kernel() {
    extern __shared__ char sgc[];
    __half* As = (__half*)sgc;
    __half* Bs = (__half*)(sgc + 128*APH*2);   // 4 slots

    const int tid  = threadIdx.x;
    const int w    = tid >> 5;
    const int lane = tid & 31;
    const int r4   = lane >> 2;
    const int c4   = lane & 3;

    const int colbase = blockIdx.x * 768;
    const int m0 = blockIdx.y * 128;
    const int b  = blockIdx.y >> 3;
    const float rstd = g_rstd[b];
    const __half* xg = g_xh + (size_t)m0 * ND;

    // group 0: A stage + B tile 0
    #pragma unroll
    for (int i = 0; i < 8; i++) {
        int q = i * 256 + tid;
        int row = q >> 4, c = (q & 15) * 8;
        cp16(&As[row*APH + c], &xg[(size_t)row * ND + c]);
    }
    load_b_async(g_win_h, colbase, Bs, tid);
    asm volatile("cp.async.commit_group;");
    asm volatile("cp.async.wait_group 0;");
    __syncthreads();

    uint32_t Ah[32];
    {
        const int rl = 16*w + r4;
        #pragma unroll
        for (int t = 0; t < 8; t++) {
            Ah[4*t+0] = *(const uint32_t*)&As[(rl    )*APH + 16*t + 2*c4    ];
            Ah[4*t+1] = *(const uint32_t*)&As[(rl + 8)*APH + 16*t + 2*c4    ];
            Ah[4*t+2] = *(const uint32_t*)&As[(rl    )*APH + 16*t + 2*c4 + 8];
            Ah[4*t+3] = *(const uint32_t*)&As[(rl + 8)*APH + 16*t + 2*c4 + 8];
        }
    }

    // prefetch B1, B2 (slots 1,2)
    load_b_async(g_win_h, colbase + 64,  Bs + 1*BSLOT, tid);
    asm volatile("cp.async.commit_group;");
    load_b_async(g_win_h, colbase + 128, Bs + 2*BSLOT, tid);
    asm volatile("cp.async.commit_group;");

    const int rlo = m0 + 16*w + r4;
    const int rhi = rlo + 8;
    const int slo = rlo & (NS - 1);
    const int shi = rhi & (NS - 1);
    const int splo = (slo & ~15) | slot16(slo & 15);
    const int sphi = (shi & ~15) | slot16(shi & 15);
    const float* offb = g_off + b * (NH*3*ND);

    #define NTQ 12
    for (int nt = 0; nt < NTQ; nt++) {
        if (nt < NTQ-2)       { asm volatile("cp.async.wait_group 2;"); }
        else if (nt == NTQ-2) { asm volatile("cp.async.wait_group 1;"); }
        else                  { asm volatile("cp.async.wait_group 0;"); }
        __syncthreads();   // protects slot (nt+3)&3 (last read iter nt-1)
        if (nt + 3 < NTQ) {
            load_b_async(g_win_h, colbase + (nt + 3) * 64,
                         Bs + ((nt + 3) & 3) * BSLOT, tid);
            asm volatile("cp.async.commit_group;");
        }
        __half* Bcur = Bs + (nt & 3) * BSLOT;

        float acc[8][4];
        #pragma unroll
        for (int j = 0; j < 8; j++)
            #pragma unroll
            for (int k = 0; k < 4; k++) acc[j][k] = 0.f;

        #pragma unroll
        for (int t = 0; t < 8; t++) {
            uint32_t a0 = Ah[4*t], a1 = Ah[4*t+1], a2 = Ah[4*t+2], a3 = Ah[4*t+3];
            #pragma unroll
            for (int j = 0; j < 8; j++) {
                uint2 bb = *(const uint2*)&Bcur[(8*j + r4)*BPH + 16*t + 4*c4];
                mma16(acc[j][0], acc[j][1], acc[j][2], acc[j][3],
                      a0, a1, a2, a3, bb.x, bb.y);
            }
        }

        // Epilogue: tile-uniform head/which/dbase; fused bias from g_off.
        const int n0 = colbase + nt * 64;
        const int hh = n0 / 384;
        const int rr = n0 - hh * 384;
        const int which = rr >> 7;
        const int dbase = (rr & 127) + 2*c4;
        const float* offp = offb + n0 + 2*c4;
        size_t base = ((size_t)(b*NH + hh)) * NS * ND;

        if (which == 0) {
            #pragma unroll
            for (int j = 0; j < 8; j++) {
                float2 off = *(const float2*)&offp[8*j];
                float v00 = rstd*acc[j][0] + off.x, v01 = rstd*acc[j][1] + off.y;
                float v10 = rstd*acc[j][2] + off.x, v11 = rstd*acc[j][3] + off.y;
                int d = dbase + 8*j;
                *(__half2*)&g_qh[base + (size_t)slo * ND + d] =
                    __floats2half2_rn(v00 * SCALE, v01 * SCALE);
                *(__half2*)&g_qh[base + (size_t)shi * ND + d] =
                    __floats2half2_rn(v10 * SCALE, v11 * SCALE);
            }
        } else if (which == 1) {
            #pragma unroll
            for (int j = 0; j < 8; j++) {
                float2 off = *(const float2*)&offp[8*j];
                float v00 = rstd*acc[j][0] + off.x, v01 = rstd*acc[j][1] + off.y;
                float v10 = rstd*acc[j][2] + off.x, v11 = rstd*acc[j][3] + off.y;
                int d = dbase + 8*j;
                int dl = d & 15;
                int sb = (dl < 8) ? (dl * 2) : ((dl - 8) * 2 + 2);
                int dp = (d & ~15) | sb;
                *(__half2*)&g_kh[base + (size_t)slo * ND + dp] = __floats2half2_rn(v00, v01);
                *(__half2*)&g_kh[base + (size_t)shi * ND + dp] = __floats2half2_rn(v10, v11);
            }
        } else {
            __half* vt = g_vth + base;
            #pragma unroll
            for (int j = 0; j < 8; j++) {
                float2 off = *(const float2*)&offp[8*j];
                float v00 = rstd*acc[j][0] + off.x, v01 = rstd*acc[j][1] + off.y;
                float v10 = rstd*acc[j][2] + off.x, v11 = rstd*acc[j][3] + off.y;
                int d = dbase + 8*j;
                vt[(size_t)d       * NS + splo] = __float2half_rn(v00);
                vt[(size_t)(d + 1) * NS + splo] = __float2half_rn(v01);
                vt[(size_t)d       * NS + sphi] = __float2half_rn(v10);
                vt[(size_t)(d + 1) * NS + sphi] = __float2half_rn(v11);
            }
        }
    }
}

// K4: out projection (unchanged from R15; 2-slot layout within same smem size)
__global__ __launch_bounds__(256, 2) void outproj_kernel(const float* __restrict__ b_out,
                                                         float* __restrict__ out) {
    extern __shared__ char sgc[];
    __half* As = (__half*)sgc;
    __half* Bs0 = (__half*)(sgc + 128*APH*2);
    __half* Bs1 = Bs0 + BSLOT;

    const int tid  = threadIdx.x;
    const int w    = tid >> 5;
    const int lane = tid & 31;
    const int r4   = lane >> 2;
    const int c4   = lane & 3;

    const int hh = blockIdx.x;
    const int m0 = blockIdx.y * 128;
    const int b  = blockIdx.y >> 3;
    const int s0 = m0 & (NS - 1);
    const __half* Ag = g_ctx + ((size_t)(b*NH + hh) * NS + s0) * ND;
    const int colbase = hh * 128;

    #pragma unroll
    for (int i = 0; i < 8; i++) {
        int q = i * 256 + tid;
        int row = q >> 4, c = (q & 15) * 8;
        cp16(&As[row*APH + c], &Ag[(size_t)row * ND + c]);
    }
    load_b_async(g_wout_h, colbase, Bs0, tid);
    asm volatile("cp.async.commit_group;");
    asm volatile("cp.async.wait_group 0;");
    __syncthreads();

    uint32_t Ah[32];
    {
        const int rl = 16*w + r4;
        #pragma unroll
        for (int t = 0; t < 8; t++) {
            Ah[4*t+0] = *(const uint32_t*)&As[(rl    )*APH + 16*t + 2*c4    ];
            Ah[4*t+1] = *(const uint32_t*)&As[(rl + 8)*APH + 16*t + 2*c4    ];
            Ah[4*t+2] = *(const uint32_t*)&As[(rl    )*APH + 16*t + 2*c4 + 8];
            Ah[4*t+3] = *(const uint32_t*)&As[(rl + 8)*APH + 16*t + 2*c4 + 8];
        }
    }

    const int rlo = m0 + 16*w + r4;
    const int rhi = rlo + 8;

    #pragma unroll
    for (int nt = 0; nt < 2; nt++) {
        __half* Bcur = nt ? Bs1 : Bs0;
        if (nt == 0) {
            load_b_async(g_wout_h, colbase + 64, Bs1, tid);
            asm volatile("cp.async.commit_group;");
        }

        float acc[8][4];
        #pragma unroll
        for (int j = 0; j < 8; j++)
            #pragma unroll
            for (int k = 0; k < 4; k++) acc[j][k] = 0.f;

        #pragma unroll
        for (int t = 0; t < 8; t++) {
            uint32_t a0 = Ah[4*t], a1 = Ah[4*t+1], a2 = Ah[4*t+2], a3 = Ah[4*t+3];
            #pragma unroll
            for (int j = 0; j < 8; j++) {
                uint2 bb = *(const uint2*)&Bcur[(8*j + r4)*BPH + 16*t + 4*c4];
                mma16(acc[j][0], acc[j][1], acc[j][2], acc[j][3],
                      a0, a1, a2, a3, bb.x, bb.y);
            }
        }

        const int n0 = colbase + nt * 64;
        #pragma unroll
        for (int j = 0; j < 8; j++) {
            int colg = n0 + 8*j + 2*c4;
            float2 bias = *(const float2*)&b_out[colg];
            *(float2*)&out[(size_t)rlo * (NH*ND) + colg] =
                make_float2(acc[j][0] + bias.x, acc[j][1] + bias.y);
            *(float2*)&out[(size_t)rhi * (NH*ND) + colg] =
                make_float2(acc[j][2] + bias.x, acc[j][3] + bias.y);
        }

        if (nt == 0) {
            asm volatile("cp.async.wait_group 0;");
            __syncthreads();
        }
    }
}

// ---------------------------------------------------------------------------
// K3: flash attention — unchanged (R10 mainloop, fp16 ctx epilogue)
// ---------------------------------------------------------------------------
#define KPH 144
#define VPH 80
#define PPH 80
#define QSH 136
#define OFF_K   0
#define OFF_V   (4*64*KPH)
#define OFF_P   (OFF_V + 4*128*VPH)
#define OFF_QSTG (OFF_V + 128*VPH)
#define ATTN_SMEM_HALVES (OFF_P + 128*PPH)

__device__ __forceinline__ void load_kv_async(const __half* __restrict__ Kg,
                                              const __half* __restrict__ Vg,
                                              int n0, __half* Ks, __half* Vt, int tid) {
    #pragma unroll
    for (int i = 0; i < 4; i++) {
        int q = i * 256 + tid;
        int kr = q >> 4, kc = (q & 15) * 8;
        cp16(&Ks[kr*KPH + kc], Kg + (size_t)(n0 + kr) * ND + kc);
        int vr = q >> 3, vc = (q & 7) * 8;
        cp16(&Vt[vr*VPH + vc], Vg + (size_t)vr * NS + n0 + vc);
    }
}

__global__ __launch_bounds__(256, 1) void attn_kernel() {
    extern __shared__ __half smh[];
    const int tid  = threadIdx.x;
    const int w    = tid >> 5;
    const int lane = tid & 31;
    const int r4   = lane >> 2;
    const int c4   = lane & 3;

    const int bh = blockIdx.x >> 3;
    const int qt = blockIdx.x & 7;
    const int h  = bh & 3;
    const int m0 = qt * 128;

    const __half* Qg = g_qh  + (size_t)bh * NS * ND;
    const __half* Kg = g_kh  + (size_t)bh * NS * ND;
    const __half* Vg = g_vth + (size_t)bh * ND * NS;

    load_kv_async(Kg, Vg, 0, smh + OFF_K, smh + OFF_V, tid);
    asm volatile("cp.async.commit_group;");

    {
        __half* Qstg = smh + OFF_QSTG;
        #pragma unroll
        for (int i = 0; i < 8; i++) {
            int q = i * 256 + tid;
            int row = q >> 4, ch = (q & 15) * 8;
            *(uint4*)&Qstg[row*QSH + ch] =
                *(const uint4*)&Qg[(size_t)(m0 + row) * ND + ch];
        }
    }
    __syncthreads();

    uint32_t Qf[32];
    {
        const __half* Qstg = smh + OFF_QSTG;
        const int rl = 16*w + r4;
        #pragma unroll
        for (int t = 0; t < 8; t++) {
            Qf[4*t+0] = *(const uint32_t*)&Qstg[(rl    )*QSH + 16*t + 2*c4    ];
            Qf[4*t+1] = *(const uint32_t*)&Qstg[(rl + 8)*QSH + 16*t + 2*c4    ];
            Qf[4*t+2] = *(const uint32_t*)&Qstg[(rl    )*QSH + 16*t + 2*c4 + 8];
            Qf[4*t+3] = *(const uint32_t*)&Qstg[(rl + 8)*QSH + 16*t + 2*c4 + 8];
        }
    }
    __syncthreads();

    load_kv_async(Kg, Vg, 64,  smh + OFF_K + 1*64*KPH, smh + OFF_V + 1*128*VPH, tid);
    asm volatile("cp.async.commit_group;");
    load_kv_async(Kg, Vg, 128, smh + OFF_K + 2*64*KPH, smh + OFF_V + 2*128*VPH, tid);
    asm volatile("cp.async.commit_group;");

    float o[16][4];
    #pragma unroll
    for (int j = 0; j < 16; j++)
        #pragma unroll
        for (int k = 0; k < 4; k++) o[j][k] = 0.f;
    float rs_lo = 0.f, rs_hi = 0.f;

    __half* Psw = smh + OFF_P + (w * 16) * PPH;
    const int mlo = m0 + 16*w + r4;
    const int mhi = mlo + 8;
    const unsigned long long* mb_lo_base = &g_mbits[((size_t)h*NS + mlo)*16];
    const unsigned long long* mb_hi_base = &g_mbits[((size_t)h*NS + mhi)*16];

    for (int it = 0; it < 16; ++it) {
        if (it < 14)       { asm volatile("cp.async.wait_group 2;"); }
        else if (it == 14) { asm volatile("cp.async.wait_group 1;"); }
        else               { asm volatile("cp.async.wait_group 0;"); }
        __syncthreads();
        if (it + 3 < 16) {
            int nslot = (it + 3) & 3;
            load_kv_async(Kg, Vg, (it + 3) * 64,
                          smh + OFF_K + nslot*64*KPH,
                          smh + OFF_V + nslot*128*VPH, tid);
            asm volatile("cp.async.commit_group;");
        }

        const __half* Ks = smh + OFF_K + (it & 3) * 64 * KPH;
        const __half* Vt = smh + OFF_V + (it & 3) * 128 * VPH;
        const unsigned long long mb_lo = mb_lo_base[it];
        const unsigned long long mb_hi = mb_hi_base[it];

        float acc[8][4];
        #pragma unroll
        for (int j = 0; j < 8; j++)
            #pragma unroll
            for (int k = 0; k < 4; k++) acc[j][k] = 0.f;

        #pragma unroll
        for (int t = 0; t < 8; t++) {
            uint32_t a0 = Qf[4*t], a1 = Qf[4*t+1], a2 = Qf[4*t+2], a3 = Qf[4*t+3];
            #pragma unroll
            for (int j = 0; j < 8; j++) {
                uint2 bb = *(const uint2*)&Ks[(8*j + r4)*KPH + 16*t + 4*c4];
                mma16(acc[j][0], acc[j][1], acc[j][2], acc[j][3],
                      a0, a1, a2, a3, bb.x, bb.y);
            }
        }

        #pragma unroll
        for (int j = 0; j < 8; j++) {
            unsigned blo = (unsigned)(mb_lo >> (8*j + 2*c4));
            unsigned bhi = (unsigned)(mb_hi >> (8*j + 2*c4));
            float p0 = (blo & 1u) ? __expf(acc[j][0]) : 0.f;
            float p1 = (blo & 2u) ? __expf(acc[j][1]) : 0.f;
            float p2 = (bhi & 1u) ? __expf(acc[j][2]) : 0.f;
            float p3 = (bhi & 2u) ? __expf(acc[j][3]) : 0.f;
            __half2 hlo = __floats2half2_rn(p0, p1);
            __half2 hhi = __floats2half2_rn(p2, p3);
            float2 flo = __half22float2(hlo);
            float2 fhi = __half22float2(hhi);
            rs_lo += flo.x + flo.y;
            rs_hi += fhi.x + fhi.y;
            int off = (j >> 1) * 16 + 4*c4 + 2*(j & 1);
            *(__half2*)&Psw[(r4    )*PPH + off] = hlo;
            *(__half2*)&Psw[(r4 + 8)*PPH + off] = hhi;
        }
        __syncwarp();

        #pragma unroll
        for (int t = 0; t < 4; t++) {
            uint2 aLo = *(const uint2*)&Psw[(r4    )*PPH + 16*t + 4*c4];
            uint2 aHi = *(const uint2*)&Psw[(r4 + 8)*PPH + 16*t + 4*c4];
            #pragma unroll
            for (int j = 0; j < 16; j++) {
                uint2 bb = *(const uint2*)&Vt[(8*j + r4)*VPH + 16*t + 4*c4];
                mma16(o[j][0], o[j][1], o[j][2], o[j][3],
                      aLo.x, aHi.x, aLo.y, aHi.y, bb.x, bb.y);
            }
        }
    }

    rs_lo += __shfl_xor_sync(0xffffffffu, rs_lo, 1);
    rs_lo += __shfl_xor_sync(0xffffffffu, rs_lo, 2);
    rs_hi += __shfl_xor_sync(0xffffffffu, rs_hi, 1);
    rs_hi += __shfl_xor_sync(0xffffffffu, rs_hi, 2);
    float inv_lo = 1.f / rs_lo;
    float inv_hi = 1.f / rs_hi;
    #pragma unroll
    for (int j = 0; j < 16; j++) {
        int d = 8*j + 2*c4;
        size_t blo = ((size_t)bh * NS + mlo) * ND + d;
        size_t bhi = ((size_t)bh * NS + mhi) * ND + d;
        *(__half2*)&g_ctx[blo] = __floats2half2_rn(o[j][0] * inv_lo, o[j][1] * inv_lo);
        *(__half2*)&g_ctx[bhi] = __floats2half2_rn(o[j][2] * inv_hi, o[j][3] * inv_hi);
    }
}

// ---------------------------------------------------------------------------
extern "C" void kernel_launch(void* const* d_in, const int* in_sizes, int n_in,
                              void* d_out, int out_size) {
    const float* x     = (const float*)d_in[0];
    const int*   edge  = (const int*)d_in[1];
    const float* W_in  = (const float*)d_in[2];
    const float* b_in  = (const float*)d_in[3];
    const float* W_out = (const float*)d_in[4];
    const float* b_out = (const float*)d_in[5];
    float* out = (float*)d_out;

    static const size_t attn_smem = ATTN_SMEM_HALVES * sizeof(__half); // 176128
    static const size_t proj_smem = PROJ_SMEM_BYTES;                   // 108544
    cudaFuncSetAttribute((const void*)attn_kernel,
                         cudaFuncAttributeMaxDynamicSharedMemorySize, (int)attn_smem);
    cudaFuncSetAttribute((const void*)qkv_kernel,
                         cudaFuncAttributeMaxDynamicSharedMemorySize, (int)proj_smem);
    cudaFuncSetAttribute((const void*)outproj_kernel,
                         cudaFuncAttributeMaxDynamicSharedMemorySize, (int)proj_smem);

    ln_partial_kernel<<<NB*8, 256>>>(x);
    ln_final_kernel<<<1, 64>>>(edge);
    prep_kernel<<<78, 256>>>(edge, W_in, b_in, W_out);
    qkv_kernel<<<dim3(2, 128), 256, proj_smem>>>();
    attn_kernel<<<NB * NH * (NS / 128), 256, attn_smem>>>();
    outproj_kernel<<<dim3(4, 128), 256, proj_smem>>>(b_out, out);
}

// round 17
// speedup vs baseline: 1.0802x; 1.0802x over previous
#include <cuda_runtime.h>
#include <cuda_fp16.h>
#include <math.h>
#include <stdint.h>

#define NB 16
#define NS 1024
#define ND 128
#define NH 4
#define LNEPS 1e-5f
#define SCALE 0.08838834764831845f

// Scratch (device globals: allocation-free per harness rules)
__device__ __half g_xh[NB*NS*ND];
__device__ __half g_qh[NB*NH*NS*ND];       // [bh][s][d], scale folded
__device__ __half g_kh[NB*NH*NS*ND];       // [bh][s][d_slot16]
__device__ __half g_vth[NB*NH*NS*ND];      // [bh][d][s_slot16]
__device__ __half g_ctx[NB*NH*NS*ND];
__device__ __half g_win_h[NH*3*ND*ND];
__device__ __half g_wout_h[NH*ND*ND];
__device__ float  g_off[NB*NH*3*ND];
__device__ float  g_psum[NB*8];
__device__ float  g_psum2[NB*8];
__device__ float  g_mean[NB];
__device__ float  g_rstd[NB];
__device__ unsigned long long g_mbits[NH*NS*16];
__device__ int    g_edge64;

__device__ __forceinline__ int slot16(int k) {
    return (k < 8) ? ((k >> 1) * 4 + (k & 1)) : (((k - 8) >> 1) * 4 + 2 + (k & 1));
}

__device__ __forceinline__ void mma16(float& d0, float& d1, float& d2, float& d3,
                                      uint32_t a0, uint32_t a1, uint32_t a2, uint32_t a3,
                                      uint32_t b0, uint32_t b1) {
    asm volatile("mma.sync.aligned.m16n8k16.row.col.f32.f16.f16.f32 "
                 "{%0,%1,%2,%3}, {%4,%5,%6,%7}, {%8,%9}, {%0,%1,%2,%3};"
                 : "+f"(d0), "+f"(d1), "+f"(d2), "+f"(d3)
                 : "r"(a0), "r"(a1), "r"(a2), "r"(a3), "r"(b0), "r"(b1));
}

__device__ __forceinline__ void cp16(void* dst_smem, const void* src_gmem) {
    uint32_t d = (uint32_t)__cvta_generic_to_shared(dst_smem);
    asm volatile("cp.async.cg.shared.global [%0], [%1], 16;" :: "r"(d), "l"(src_gmem));
}

__device__ __forceinline__ uint32_t h2u(__half2 h) {
    return *reinterpret_cast<uint32_t*>(&h);
}

// ---------------------------------------------------------------------------
// K1a: LN partial sums + fp16 x copy
// ---------------------------------------------------------------------------
__global__ void ln_partial_kernel(const float* __restrict__ x) {
    const int b = blockIdx.x >> 3;
    const int part = blockIdx.x & 7;
    const size_t base4 = (size_t)b * NS * ND / 4 + part * 4096;
    const float4* xb = (const float4*)x + base4;
    __half2* xh = (__half2*)g_xh + base4 * 2;
    float s = 0.f, ss = 0.f;
    #pragma unroll
    for (int i = 0; i < 16; i++) {
        float4 v = xb[i * 256 + threadIdx.x];
        s  += v.x + v.y + v.z + v.w;
        ss += v.x*v.x + v.y*v.y + v.z*v.z + v.w*v.w;
        xh[2*(i*256 + threadIdx.x)]     = __floats2half2_rn(v.x, v.y);
        xh[2*(i*256 + threadIdx.x) + 1] = __floats2half2_rn(v.z, v.w);
    }
    __shared__ float sh[256], sh2[256];
    sh[threadIdx.x] = s; sh2[threadIdx.x] = ss;
    __syncthreads();
    for (int o = 128; o > 0; o >>= 1) {
        if (threadIdx.x < o) {
            sh[threadIdx.x]  += sh[threadIdx.x + o];
            sh2[threadIdx.x] += sh2[threadIdx.x + o];
        }
        __syncthreads();
    }
    if (threadIdx.x == 0) {
        g_psum[blockIdx.x]  = sh[0];
        g_psum2[blockIdx.x] = sh2[0];
    }
}

__global__ void ln_final_kernel(const int* __restrict__ edge) {
    int t = threadIdx.x;
    if (t < NB) {
        float s = 0.f, ss = 0.f;
        #pragma unroll
        for (int i = 0; i < 8; i++) { s += g_psum[t*8 + i]; ss += g_psum2[t*8 + i]; }
        float inv_n = 1.f / (float)(NS * ND);
        float mu  = s * inv_n;
        float var = ss * inv_n - mu * mu;
        g_mean[t] = mu;
        g_rstd[t] = rsqrtf(var + LNEPS);
    } else if (t == 32) {
        int any = 0;
        #pragma unroll
        for (int i = 0; i < 64; i++) any |= edge[2*i + 1];
        g_edge64 = (any == 0) ? 1 : 0;
    }
}

// ---------------------------------------------------------------------------
// K1c: prep — bitmasks, fused bias, fp16 slot16 weights
// ---------------------------------------------------------------------------
__global__ void prep_kernel(const int* __restrict__ edge,
                            const float* __restrict__ W_in,
                            const float* __restrict__ b_in,
                            const float* __restrict__ W_out) {
    int blk = blockIdx.x;
    if (blk < 64) {
        int idx = blk * 256 + threadIdx.x;
        int s = idx >> 4, t64 = idx & 15;
        unsigned long long m0 = 0, m1 = 0, m2 = 0, m3 = 0;
        if (g_edge64) {
            const int4* p = (const int4*)(edge + 2*((size_t)s*NS + t64*64));
            #pragma unroll
            for (int i = 0; i < 32; i++) {
                int4 v = p[i];
                unsigned long long b0 = 1ull << (2*i), b1 = 1ull << (2*i+1);
                if (v.x == 1) m0 |= b0;  if (v.z == 1) m0 |= b1;
                if (v.x == 2) m1 |= b0;  if (v.z == 2) m1 |= b1;
                if (v.x == 3) m2 |= b0;  if (v.z == 3) m2 |= b1;
                if (v.x == 4) m3 |= b0;  if (v.z == 4) m3 |= b1;
            }
        } else {
            const int4* p = (const int4*)(edge + ((size_t)s*NS + t64*64));
            #pragma unroll
            for (int i = 0; i < 16; i++) {
                int4 v = p[i];
                int e[4] = {v.x, v.y, v.z, v.w};
                #pragma unroll
                for (int q = 0; q < 4; q++) {
                    unsigned long long b = 1ull << (4*i + q);
                    if (e[q] == 1) m0 |= b;
                    if (e[q] == 2) m1 |= b;
                    if (e[q] == 3) m2 |= b;
                    if (e[q] == 4) m3 |= b;
                }
            }
        }
        g_mbits[(0*NS + s)*16 + t64] = m0;
        g_mbits[(1*NS + s)*16 + t64] = m1;
        g_mbits[(2*NS + s)*16 + t64] = m2;
        g_mbits[(3*NS + s)*16 + t64] = m3;
    } else if (blk < 70) {
        int col = (blk - 64) * 256 + threadIdx.x;
        float s = 0.f;
        const float4* p = (const float4*)(W_in + (size_t)col * ND);
        #pragma unroll
        for (int i = 0; i < 32; i++) {
            float4 v = p[i];
            s += v.x + v.y + v.z + v.w;
        }
        float bias = b_in[col];
        #pragma unroll
        for (int bb = 0; bb < NB; bb++) {
            float mr = g_mean[bb] * g_rstd[bb];
            g_off[bb * (NH*3*ND) + col] = bias - mr * s;
        }
    } else {
        int row = (blk - 70) * 256 + threadIdx.x;
        const float* src;
        __half* dst;
        if (row < 1536) { src = W_in  + (size_t)row * ND;          dst = g_win_h  + (size_t)row * ND; }
        else            { src = W_out + (size_t)(row - 1536) * ND; dst = g_wout_h + (size_t)(row - 1536) * ND; }
        #pragma unroll
        for (int g = 0; g < 8; g++) {
            float4 A0 = *(const float4*)&src[16*g];
            float4 A1 = *(const float4*)&src[16*g + 4];
            float4 A2 = *(const float4*)&src[16*g + 8];
            float4 A3 = *(const float4*)&src[16*g + 12];
            __half2 h[8];
            h[0] = __floats2half2_rn(A0.x, A0.y);
            h[1] = __floats2half2_rn(A2.x, A2.y);
            h[2] = __floats2half2_rn(A0.z, A0.w);
            h[3] = __floats2half2_rn(A2.z, A2.w);
            h[4] = __floats2half2_rn(A1.x, A1.y);
            h[5] = __floats2half2_rn(A3.x, A3.y);
            h[6] = __floats2half2_rn(A1.z, A1.w);
            h[7] = __floats2half2_rn(A3.z, A3.w);
            *(uint4*)&dst[16*g]     = *(const uint4*)&h[0];
            *(uint4*)&dst[16*g + 8] = *(const uint4*)&h[4];
        }
    }
}

// ---------------------------------------------------------------------------
// Projection kernels (unchanged from R16)
// ---------------------------------------------------------------------------
#define APH 136
#define BPH 144
#define BSLOT (64*BPH)
#define PROJ_SMEM_BYTES (128*APH*2 + 4*64*BPH*2)

__device__ __forceinline__ void load_b_async(const __half* __restrict__ Wsrc,
                                             int rowbase, __half* Bslot, int tid) {
    #pragma unroll
    for (int i = 0; i < 4; i++) {
        int q = i * 256 + tid;
        int row = q >> 4, c = (q & 15) * 8;
        cp16(&Bslot[row*BPH + c], &Wsrc[(size_t)(rowbase + row) * ND + c]);
    }
}

__global__ __launch_bounds__(256, 2) void qkv_kernel() {
    extern __shared__ char sgc[];
    __half* As = (__half*)sgc;
    __half* Bs = (__half*)(sgc + 128*APH*2);

    const int tid  = threadIdx.x;
    const int w    = tid >> 5;
    const int lane = tid & 31;
    const int r4   = lane >> 2;
    const int c4   = lane & 3;

    const int colbase = blockIdx.x * 768;
    const int m0 = blockIdx.y * 128;
    const int b  = blockIdx.y >> 3;
    const float rstd = g_rstd[b];
    const __half* xg = g_xh + (size_t)m0 * ND;

    #pragma unroll
    for (int i = 0; i < 8; i++) {
        int q = i * 256 + tid;
        int row = q >> 4, c = (q & 15) * 8;
        cp16(&As[row*APH + c], &xg[(size_t)row * ND + c]);
    }
    load_b_async(g_win_h, colbase, Bs, tid);
    asm volatile("cp.async.commit_group;");
    asm volatile("cp.async.wait_group 0;");
    __syncthreads();

    uint32_t Ah[32];
    {
        const int rl = 16*w + r4;
        #pragma unroll
        for (int t = 0; t < 8; t++) {
            Ah[4*t+0] = *(const uint32_t*)&As[(rl    )*APH + 16*t + 2*c4    ];
            Ah[4*t+1] = *(const uint32_t*)&As[(rl + 8)*APH + 16*t + 2*c4    ];
            Ah[4*t+2] = *(const uint32_t*)&As[(rl    )*APH + 16*t + 2*c4 + 8];
            Ah[4*t+3] = *(const uint32_t*)&As[(rl + 8)*APH + 16*t + 2*c4 + 8];
        }
    }

    load_b_async(g_win_h, colbase + 64,  Bs + 1*BSLOT, tid);
    asm volatile("cp.async.commit_group;");
    load_b_async(g_win_h, colbase + 128, Bs + 2*BSLOT, tid);
    asm volatile("cp.async.commit_group;");

    const int rlo = m0 + 16*w + r4;
    const int rhi = rlo + 8;
    const int slo = rlo & (NS - 1);
    const int shi = rhi & (NS - 1);
    const int splo = (slo & ~15) | slot16(slo & 15);
    const int sphi = (shi & ~15) | slot16(shi & 15);
    const float* offb = g_off + b * (NH*3*ND);

    #define NTQ 12
    for (int nt = 0; nt < NTQ; nt++) {
        if (nt < NTQ-2)       { asm volatile("cp.async.wait_group 2;"); }
        else if (nt == NTQ-2) { asm volatile("cp.async.wait_group 1;"); }
        else                  { asm volatile("cp.async.wait_group 0;"); }
        __syncthreads();
        if (nt + 3 < NTQ) {
            load_b_async(g_win_h, colbase + (nt + 3) * 64,
                         Bs + ((nt + 3) & 3) * BSLOT, tid);
            asm volatile("cp.async.commit_group;");
        }
        __half* Bcur = Bs + (nt & 3) * BSLOT;

        float acc[8][4];
        #pragma unroll
        for (int j = 0; j < 8; j++)
            #pragma unroll
            for (int k = 0; k < 4; k++) acc[j][k] = 0.f;

        #pragma unroll
        for (int t = 0; t < 8; t++) {
            uint32_t a0 = Ah[4*t], a1 = Ah[4*t+1], a2 = Ah[4*t+2], a3 = Ah[4*t+3];
            #pragma unroll
            for (int j = 0; j < 8; j++) {
                uint2 bb = *(const uint2*)&Bcur[(8*j + r4)*BPH + 16*t + 4*c4];
                mma16(acc[j][0], acc[j][1], acc[j][2], acc[j][3],
                      a0, a1, a2, a3, bb.x, bb.y);
            }
        }

        const int n0 = colbase + nt * 64;
        const int hh = n0 / 384;
        const int rr = n0 - hh * 384;
        const int which = rr >> 7;
        const int dbase = (rr & 127) + 2*c4;
        const float* offp = offb + n0 + 2*c4;
        size_t base = ((size_t)(b*NH + hh)) * NS * ND;

        if (which == 0) {
            #pragma unroll
            for (int j = 0; j < 8; j++) {
                float2 off = *(const float2*)&offp[8*j];
                float v00 = rstd*acc[j][0] + off.x, v01 = rstd*acc[j][1] + off.y;
                float v10 = rstd*acc[j][2] + off.x, v11 = rstd*acc[j][3] + off.y;
                int d = dbase + 8*j;
                *(__half2*)&g_qh[base + (size_t)slo * ND + d] =
                    __floats2half2_rn(v00 * SCALE, v01 * SCALE);
                *(__half2*)&g_qh[base + (size_t)shi * ND + d] =
                    __floats2half2_rn(v10 * SCALE, v11 * SCALE);
            }
        } else if (which == 1) {
            #pragma unroll
            for (int j = 0; j < 8; j++) {
                float2 off = *(const float2*)&offp[8*j];
                float v00 = rstd*acc[j][0] + off.x, v01 = rstd*acc[j][1] + off.y;
                float v10 = rstd*acc[j][2] + off.x, v11 = rstd*acc[j][3] + off.y;
                int d = dbase + 8*j;
                int dl = d & 15;
                int sb = (dl < 8) ? (dl * 2) : ((dl - 8) * 2 + 2);
                int dp = (d & ~15) | sb;
                *(__half2*)&g_kh[base + (size_t)slo * ND + dp] = __floats2half2_rn(v00, v01);
                *(__half2*)&g_kh[base + (size_t)shi * ND + dp] = __floats2half2_rn(v10, v11);
            }
        } else {
            __half* vt = g_vth + base;
            #pragma unroll
            for (int j = 0; j < 8; j++) {
                float2 off = *(const float2*)&offp[8*j];
                float v00 = rstd*acc[j][0] + off.x, v01 = rstd*acc[j][1] + off.y;
                float v10 = rstd*acc[j][2] + off.x, v11 = rstd*acc[j][3] + off.y;
                int d = dbase + 8*j;
                vt[(size_t)d       * NS + splo] = __float2half_rn(v00);
                vt[(size_t)(d + 1) * NS + splo] = __float2half_rn(v01);
                vt[(size_t)d       * NS + sphi] = __float2half_rn(v10);
                vt[(size_t)(d + 1) * NS + sphi] = __float2half_rn(v11);
            }
        }
    }
}

__global__ __launch_bounds__(256, 2) void outproj_kernel(const float* __restrict__ b_out,
                                                         float* __restrict__ out) {
    extern __shared__ char sgc[];
    __half* As = (__half*)sgc;
    __half* Bs0 = (__half*)(sgc + 128*APH*2);
    __half* Bs1 = Bs0 + BSLOT;

    const int tid  = threadIdx.x;
    const int w    = tid >> 5;
    const int lane = tid & 31;
    const int r4   = lane >> 2;
    const int c4   = lane & 3;

    const int hh = blockIdx.x;
    const int m0 = blockIdx.y * 128;
    const int b  = blockIdx.y >> 3;
    const int s0 = m0 & (NS - 1);
    const __half* Ag = g_ctx + ((size_t)(b*NH + hh) * NS + s0) * ND;
    const int colbase = hh * 128;

    #pragma unroll
    for (int i = 0; i < 8; i++) {
        int q = i * 256 + tid;
        int row = q >> 4, c = (q & 15) * 8;
        cp16(&As[row*APH + c], &Ag[(size_t)row * ND + c]);
    }
    load_b_async(g_wout_h, colbase, Bs0, tid);
    asm volatile("cp.async.commit_group;");
    asm volatile("cp.async.wait_group 0;");
    __syncthreads();

    uint32_t Ah[32];
    {
        const int rl = 16*w + r4;
        #pragma unroll
        for (int t = 0; t < 8; t++) {
            Ah[4*t+0] = *(const uint32_t*)&As[(rl    )*APH + 16*t + 2*c4    ];
            Ah[4*t+1] = *(const uint32_t*)&As[(rl + 8)*APH + 16*t + 2*c4    ];
            Ah[4*t+2] = *(const uint32_t*)&As[(rl    )*APH + 16*t + 2*c4 + 8];
            Ah[4*t+3] = *(const uint32_t*)&As[(rl + 8)*APH + 16*t + 2*c4 + 8];
        }
    }

    const int rlo = m0 + 16*w + r4;
    const int rhi = rlo + 8;

    #pragma unroll
    for (int nt = 0; nt < 2; nt++) {
        __half* Bcur = nt ? Bs1 : Bs0;
        if (nt == 0) {
            load_b_async(g_wout_h, colbase + 64, Bs1, tid);
            asm volatile("cp.async.commit_group;");
        }

        float acc[8][4];
        #pragma unroll
        for (int j = 0; j < 8; j++)
            #pragma unroll
            for (int k = 0; k < 4; k++) acc[j][k] = 0.f;

        #pragma unroll
        for (int t = 0; t < 8; t++) {
            uint32_t a0 = Ah[4*t], a1 = Ah[4*t+1], a2 = Ah[4*t+2], a3 = Ah[4*t+3];
            #pragma unroll
            for (int j = 0; j < 8; j++) {
                uint2 bb = *(const uint2*)&Bcur[(8*j + r4)*BPH + 16*t + 4*c4];
                mma16(acc[j][0], acc[j][1], acc[j][2], acc[j][3],
                      a0, a1, a2, a3, bb.x, bb.y);
            }
        }

        const int n0 = colbase + nt * 64;
        #pragma unroll
        for (int j = 0; j < 8; j++) {
            int colg = n0 + 8*j + 2*c4;
            float2 bias = *(const float2*)&b_out[colg];
            *(float2*)&out[(size_t)rlo * (NH*ND) + colg] =
                make_float2(acc[j][0] + bias.x, acc[j][1] + bias.y);
            *(float2*)&out[(size_t)rhi * (NH*ND) + colg] =
                make_float2(acc[j][2] + bias.x, acc[j][3] + bias.y);
        }

        if (nt == 0) {
            asm volatile("cp.async.wait_group 0;");
            __syncthreads();
        }
    }
}

// ---------------------------------------------------------------------------
// K3: warp-specialized flash attention. 64-row Q tiles, 2 CTAs/SM.
// Warps 0-3: QK+softmax producers. Warps 4-7: PV consumers.
// Rendezvous barrier per pair (ids 1-4); group bars 9 (prod), 10 (cons);
// rs handoff via bar 11.
// ---------------------------------------------------------------------------
#define KPH 144
#define VPH 80
#define PPH 80
#define QSH 136
#define A_OFF_K   0
#define A_OFF_V   (2*64*KPH)                 // 18432
#define A_OFF_P   (A_OFF_V + 2*128*VPH)      // 38912
#define A_OFF_RS  (A_OFF_P + 2*4*16*PPH)     // 49152
#define ATTN_SMEM_HALVES (A_OFF_RS + 256)    // 49408 halves = 98816 B
#define A_OFF_QSTG A_OFF_V                   // Q staging overlaps V slot 0

__global__ __launch_bounds__(256, 2) void attn_kernel() {
    extern __shared__ __half smh[];
    const int tid  = threadIdx.x;
    const int w    = tid >> 5;
    const int lane = tid & 31;
    const int r4   = lane >> 2;
    const int c4   = lane & 3;
    const int tp   = tid & 127;

    const int bh = blockIdx.x >> 4;
    const int qt = blockIdx.x & 15;
    const int h  = bh & 3;
    const int m0 = qt * 64;

    const __half* Qg = g_qh  + (size_t)bh * NS * ND;
    const __half* Kg = g_kh  + (size_t)bh * NS * ND;
    const __half* Vg = g_vth + (size_t)bh * ND * NS;
    float* rsf = (float*)(smh + A_OFF_RS);

    const bool producer = (w < 4);
    const int rg = producer ? w : (w - 4);

    // producers issue K tile 0 (slot 0)
    if (producer) {
        #pragma unroll
        for (int i = 0; i < 8; i++) {
            int q = i * 128 + tp;
            int kr = q >> 4, kc = (q & 15) * 8;
            cp16(&smh[A_OFF_K + kr*KPH + kc], Kg + (size_t)kr * ND + kc);
        }
        asm volatile("cp.async.commit_group;");
    }

    // all threads stage Q (64 rows x 128 halves)
    {
        __half* Qstg = smh + A_OFF_QSTG;
        #pragma unroll
        for (int i = 0; i < 4; i++) {
            int q = i * 256 + tid;
            int row = q >> 4, ch = (q & 15) * 8;
            *(uint4*)&Qstg[row*QSH + ch] =
                *(const uint4*)&Qg[(size_t)(m0 + row) * ND + ch];
        }
    }
    __syncthreads();

    uint32_t Qf[32];
    if (producer) {
        const __half* Qstg = smh + A_OFF_QSTG;
        const int rl = 16*rg + r4;
        #pragma unroll
        for (int t = 0; t < 8; t++) {
            Qf[4*t+0] = *(const uint32_t*)&Qstg[(rl    )*QSH + 16*t + 2*c4    ];
            Qf[4*t+1] = *(const uint32_t*)&Qstg[(rl + 8)*QSH + 16*t + 2*c4    ];
            Qf[4*t+2] = *(const uint32_t*)&Qstg[(rl    )*QSH + 16*t + 2*c4 + 8];
            Qf[4*t+3] = *(const uint32_t*)&Qstg[(rl + 8)*QSH + 16*t + 2*c4 + 8];
        }
    }
    __syncthreads();   // Q staging region (V slot 0) may now be overwritten

    if (producer) {
        float rs_lo = 0.f, rs_hi = 0.f;
        const int mlo = m0 + 16*rg + r4;
        const int mhi = mlo + 8;
        const unsigned long long* mb_lo_base = &g_mbits[((size_t)h*NS + mlo)*16];
        const unsigned long long* mb_hi_base = &g_mbits[((size_t)h*NS + mhi)*16];

        for (int it = 0; it < 16; ++it) {
            if (it > 0) asm volatile("bar.sync 9, 128;");
            if (it + 1 < 16) {
                const __half* Ksrc = Kg + (size_t)(it + 1) * 64 * ND;
                __half* Kdst = smh + A_OFF_K + ((it + 1) & 1) * 64 * KPH;
                #pragma unroll
                for (int i = 0; i < 8; i++) {
                    int q = i * 128 + tp;
                    int kr = q >> 4, kc = (q & 15) * 8;
                    cp16(&Kdst[kr*KPH + kc], Ksrc + (size_t)kr * ND + kc);
                }
                asm volatile("cp.async.commit_group;");
                asm volatile("cp.async.wait_group 1;");
            } else {
                asm volatile("cp.async.wait_group 0;");
            }

            const __half* Ks = smh + A_OFF_K + (it & 1) * 64 * KPH;
            const unsigned long long mb_lo = mb_lo_base[it];
            const unsigned long long mb_hi = mb_hi_base[it];

            float acc[8][4];
            #pragma unroll
            for (int j = 0; j < 8; j++)
                #pragma unroll
                for (int k = 0; k < 4; k++) acc[j][k] = 0.f;

            #pragma unroll
            for (int t = 0; t < 8; t++) {
                uint32_t a0 = Qf[4*t], a1 = Qf[4*t+1], a2 = Qf[4*t+2], a3 = Qf[4*t+3];
                #pragma unroll
                for (int j = 0; j < 8; j++) {
                    uint2 bb = *(const uint2*)&Ks[(8*j + r4)*KPH + 16*t + 4*c4];
                    mma16(acc[j][0], acc[j][1], acc[j][2], acc[j][3],
                          a0, a1, a2, a3, bb.x, bb.y);
                }
            }

            __half* Psw = smh + A_OFF_P + ((it & 1) * 4 + rg) * 16 * PPH;
            #pragma unroll
            for (int j = 0; j < 8; j++) {
                unsigned blo = (unsigned)(mb_lo >> (8*j + 2*c4));
                unsigned bhi = (unsigned)(mb_hi >> (8*j + 2*c4));
                float p0 = (blo & 1u) ? __expf(acc[j][0]) : 0.f;
                float p1 = (blo & 2u) ? __expf(acc[j][1]) : 0.f;
                float p2 = (bhi & 1u) ? __expf(acc[j][2]) : 0.f;
                float p3 = (bhi & 2u) ? __expf(acc[j][3]) : 0.f;
                __half2 hlo = __floats2half2_rn(p0, p1);
                __half2 hhi = __floats2half2_rn(p2, p3);
                float2 flo = __half22float2(hlo);
                float2 fhi = __half22float2(hhi);
                rs_lo += flo.x + flo.y;
                rs_hi += fhi.x + fhi.y;
                int off = (j >> 1) * 16 + 4*c4 + 2*(j & 1);
                *(__half2*)&Psw[(r4    )*PPH + off] = hlo;
                *(__half2*)&Psw[(r4 + 8)*PPH + off] = hhi;
            }
            // rendezvous with partner consumer: P(it) published
            asm volatile("bar.sync %0, 64;" :: "r"(1 + rg));
        }

        rs_lo += __shfl_xor_sync(0xffffffffu, rs_lo, 1);
        rs_lo += __shfl_xor_sync(0xffffffffu, rs_lo, 2);
        rs_hi += __shfl_xor_sync(0xffffffffu, rs_hi, 1);
        rs_hi += __shfl_xor_sync(0xffffffffu, rs_hi, 2);
        if (c4 == 0) {
            rsf[rg*16 + r4]     = rs_lo;
            rsf[rg*16 + 8 + r4] = rs_hi;
        }
        __threadfence_block();
        asm volatile("bar.arrive 11, 256;");
    } else {
        float o[16][4];
        #pragma unroll
        for (int j = 0; j < 16; j++)
            #pragma unroll
            for (int k = 0; k < 4; k++) o[j][k] = 0.f;

        // pre-load V tile 0 (slot 0)
        #pragma unroll
        for (int i = 0; i < 8; i++) {
            int q = i * 128 + tp;
            int vr = q >> 3, vc = (q & 7) * 8;
            cp16(&smh[A_OFF_V + vr*VPH + vc], Vg + (size_t)vr * NS + vc);
        }
        asm volatile("cp.async.commit_group;");

        for (int it = 0; it < 16; ++it) {
            if (it > 0) asm volatile("bar.sync 10, 128;");
            if (it + 1 < 16) {
                __half* Vdst = smh + A_OFF_V + ((it + 1) & 1) * 128 * VPH;
                const int n0n = (it + 1) * 64;
                #pragma unroll
                for (int i = 0; i < 8; i++) {
                    int q = i * 128 + tp;
                    int vr = q >> 3, vc = (q & 7) * 8;
                    cp16(&Vdst[vr*VPH + vc], Vg + (size_t)vr * NS + n0n + vc);
                }
                asm volatile("cp.async.commit_group;");
                asm volatile("cp.async.wait_group 1;");
            } else {
                asm volatile("cp.async.wait_group 0;");
            }

            // rendezvous: P(it) ready from partner producer
            asm volatile("bar.sync %0, 64;" :: "r"(1 + rg));

            const __half* Vt = smh + A_OFF_V + (it & 1) * 128 * VPH;
            const __half* Psw = smh + A_OFF_P + ((it & 1) * 4 + rg) * 16 * PPH;
            #pragma unroll
            for (int t = 0; t < 4; t++) {
                uint2 aLo = *(const uint2*)&Psw[(r4    )*PPH + 16*t + 4*c4];
                uint2 aHi = *(const uint2*)&Psw[(r4 + 8)*PPH + 16*t + 4*c4];
                #pragma unroll
                for (int j = 0; j < 16; j++) {
                    uint2 bb = *(const uint2*)&Vt[(8*j + r4)*VPH + 16*t + 4*c4];
                    mma16(o[j][0], o[j][1], o[j][2], o[j][3],
                          aLo.x, aHi.x, aLo.y, aHi.y, bb.x, bb.y);
                }
            }
        }

        // wait for producers' rowsums
        asm volatile("bar.sync 11, 256;");
        const int mlo = m0 + 16*rg + r4;
        const int mhi = mlo + 8;
        float inv_lo = 1.f / rsf[rg*16 + r4];
        float inv_hi = 1.f / rsf[rg*16 + 8 + r4];
        #pragma unroll
        for (int j = 0; j < 16; j++) {
            int d = 8*j + 2*c4;
            size_t blo = ((size_t)bh * NS + mlo) * ND + d;
            size_t bhi = ((size_t)bh * NS + mhi) * ND + d;
            *(__half2*)&g_ctx[blo] = __floats2half2_rn(o[j][0] * inv_lo, o[j][1] * inv_lo);
            *(__half2*)&g_ctx[bhi] = __floats2half2_rn(o[j][2] * inv_hi, o[j][3] * inv_hi);
        }
    }
}

// ---------------------------------------------------------------------------
extern "C" void kernel_launch(void* const* d_in, const int* in_sizes, int n_in,
                              void* d_out, int out_size) {
    const float* x     = (const float*)d_in[0];
    const int*   edge  = (const int*)d_in[1];
    const float* W_in  = (const float*)d_in[2];
    const float* b_in  = (const float*)d_in[3];
    const float* W_out = (const float*)d_in[4];
    const float* b_out = (const float*)d_in[5];
    float* out = (float*)d_out;

    static const size_t attn_smem = ATTN_SMEM_HALVES * sizeof(__half); // 98816
    static const size_t proj_smem = PROJ_SMEM_BYTES;                   // 108544
    cudaFuncSetAttribute((const void*)attn_kernel,
                         cudaFuncAttributeMaxDynamicSharedMemorySize, (int)attn_smem);
    cudaFuncSetAttribute((const void*)qkv_kernel,
                         cudaFuncAttributeMaxDynamicSharedMemorySize, (int)proj_smem);
    cudaFuncSetAttribute((const void*)outproj_kernel,
                         cudaFuncAttributeMaxDynamicSharedMemorySize, (int)proj_smem);

    ln_partial_kernel<<<NB*8, 256>>>(x);
    ln_final_kernel<<<1, 64>>>(edge);
    prep_kernel<<<78, 256>>>(edge, W_in, b_in, W_out);
    qkv_kernel<<<dim3(2, 128), 256, proj_smem>>>();
    attn_kernel<<<NB * NH * (NS / 64), 256, attn_smem>>>();
    outproj_kernel<<<dim3(4, 128), 256, proj_smem>>>(b_out, out);
}